// round 1
// baseline (speedup 1.0000x reference)
#include <cuda_runtime.h>

#define Bb 2
#define Hh 16
#define Ss 2048
#define Dd 128
#define BM 64
#define BN 64
#define NT 256
#define KSTRIDE 132   // 128 + 4 pad: kills K-load bank conflicts, keeps 16B align
#define PSTRIDE 68    // 64 + 4 pad
#define SMEM_FLOATS (2*BM*KSTRIDE + BM*PSTRIDE)
#define SMEM_BYTES (SMEM_FLOATS*4)

__device__ int g_len[Bb];
__device__ int g_off;

// Derive per-batch valid lengths from the padding mask, robust to the mask's
// storage width (bool->uint8 vs int32/float32). lengths >= S/2 guarantees
// element 1 is "true": byte[1]!=0 => 1-byte elements; ==0 => 4-byte elements.
__global__ void prep_kernel(const unsigned char* __restrict__ mask, const int* offp) {
    int b = blockIdx.x;
    __shared__ int cnt;
    if (threadIdx.x == 0) cnt = 0;
    __syncthreads();
    bool w4 = (mask[1] == 0);
    int local = 0;
    for (int j = threadIdx.x; j < Ss; j += blockDim.x) {
        bool valid;
        if (w4) valid = (((const unsigned int*)mask)[(size_t)b * Ss + j] != 0u);
        else    valid = (mask[(size_t)b * Ss + j] != 0);
        local += valid ? 1 : 0;
    }
    atomicAdd(&cnt, local);
    __syncthreads();
    if (threadIdx.x == 0) {
        g_len[b] = cnt;
        if (b == 0) g_off = offp ? offp[0] : 0;
    }
}

__global__ __launch_bounds__(NT, 2)
void attend_kernel(const float* __restrict__ Q, const float* __restrict__ K,
                   const float* __restrict__ V, const float* __restrict__ Bias,
                   float* __restrict__ Out) {
    extern __shared__ float smem[];
    float* Qs = smem;                    // [64][132]
    float* Ks = smem + BM * KSTRIDE;     // [64][132], reused for V
    float* Ps = smem + 2 * BM * KSTRIDE; // [64][68]

    const int tid = threadIdx.x;
    const int ty = tid >> 4;   // 0..15 -> q-row group
    const int tx = tid & 15;   // 0..15 -> key-col / out-col group
    const int bh = blockIdx.y;
    const int b = bh / Hh;
    const int h = bh - b * Hh;
    const int q0 = blockIdx.x * BM;

    const int L   = g_len[b];
    const int off = g_off;

    const float* qb = Q + ((size_t)bh * Ss + q0) * Dd;
    const float* kb = K + (size_t)bh * Ss * Dd;
    const float* vb = V + (size_t)bh * Ss * Dd;
    const float* bb = Bias + (size_t)h * Ss * Ss;
    float* ob = Out + ((size_t)bh * Ss + q0) * Dd;

    // Load Q tile (64 x 128), float4 coalesced
    #pragma unroll
    for (int t = tid; t < BM * (Dd / 4); t += NT) {
        int r = t >> 5, c4 = t & 31;
        float4 val = ((const float4*)(qb + (size_t)r * Dd))[c4];
        *(float4*)&Qs[r * KSTRIDE + c4 * 4] = val;
    }

    float m[4], l[4], O[4][8];
    #pragma unroll
    for (int a = 0; a < 4; a++) {
        m[a] = -1e30f; l[a] = 0.f;
        #pragma unroll
        for (int j = 0; j < 8; j++) O[a][j] = 0.f;
    }

    // causal + padding tile bound: keys j <= i - off, j < L
    int maxj = q0 + BM - 1 - off;
    if (maxj > L - 1) maxj = L - 1;
    const int ntiles = (maxj >= 0) ? (maxj / BN + 1) : 0;

    const float scale = 0.08838834764831845f;  // 128^-0.5

    for (int t = 0; t < ntiles; ++t) {
        const int n0 = t * BN;
        __syncthreads();  // previous iter done reading Ks/Ps
        // Load K tile
        #pragma unroll
        for (int tt = tid; tt < BN * (Dd / 4); tt += NT) {
            int r = tt >> 5, c4 = tt & 31;
            float4 val = ((const float4*)(kb + (size_t)(n0 + r) * Dd))[c4];
            *(float4*)&Ks[r * KSTRIDE + c4 * 4] = val;
        }
        __syncthreads();

        // S = Q @ K^T (register-tiled 4x4, vectorized over d)
        float acc[4][4];
        #pragma unroll
        for (int a = 0; a < 4; a++)
            #pragma unroll
            for (int c = 0; c < 4; c++) acc[a][c] = 0.f;

        #pragma unroll 8
        for (int d = 0; d < Dd; d += 4) {
            float4 qv[4], kv[4];
            #pragma unroll
            for (int a = 0; a < 4; a++)
                qv[a] = *(const float4*)&Qs[(ty + 16 * a) * KSTRIDE + d];
            #pragma unroll
            for (int c = 0; c < 4; c++)
                kv[c] = *(const float4*)&Ks[(tx + 16 * c) * KSTRIDE + d];
            #pragma unroll
            for (int a = 0; a < 4; a++)
                #pragma unroll
                for (int c = 0; c < 4; c++) {
                    acc[a][c] = fmaf(qv[a].x, kv[c].x, acc[a][c]);
                    acc[a][c] = fmaf(qv[a].y, kv[c].y, acc[a][c]);
                    acc[a][c] = fmaf(qv[a].z, kv[c].z, acc[a][c]);
                    acc[a][c] = fmaf(qv[a].w, kv[c].w, acc[a][c]);
                }
        }

        const bool full = (n0 + BN - 1 <= q0 - off) && (n0 + BN <= L);

        float s[4][4];
        #pragma unroll
        for (int a = 0; a < 4; a++) {
            const int i = q0 + ty + 16 * a;
            #pragma unroll
            for (int c = 0; c < 4; c++) {
                const int j = n0 + tx + 16 * c;
                if (full || ((j <= i - off) && (j < L)))
                    s[a][c] = acc[a][c] * scale + __ldg(&bb[(size_t)i * Ss + j]);
                else
                    s[a][c] = -1e30f;
            }
        }

        // Online softmax (row spread over 16 lanes; width-16 shuffles)
        #pragma unroll
        for (int a = 0; a < 4; a++) {
            float mx = fmaxf(fmaxf(s[a][0], s[a][1]), fmaxf(s[a][2], s[a][3]));
            #pragma unroll
            for (int w = 8; w >= 1; w >>= 1)
                mx = fmaxf(mx, __shfl_xor_sync(0xFFFFFFFFu, mx, w, 16));
            float mnew  = fmaxf(m[a], mx);
            float alpha = __expf(m[a] - mnew);
            float sum = 0.f;
            #pragma unroll
            for (int c = 0; c < 4; c++) {
                float p = __expf(s[a][c] - mnew);
                sum += p;
                Ps[(ty + 16 * a) * PSTRIDE + tx + 16 * c] = p;
            }
            #pragma unroll
            for (int w = 8; w >= 1; w >>= 1)
                sum += __shfl_xor_sync(0xFFFFFFFFu, sum, w, 16);
            l[a] = l[a] * alpha + sum;
            m[a] = mnew;
            #pragma unroll
            for (int j = 0; j < 8; j++) O[a][j] *= alpha;
        }

        __syncthreads();  // Ps fully written; Ks free
        // Load V tile into the K buffer
        #pragma unroll
        for (int tt = tid; tt < BN * (Dd / 4); tt += NT) {
            int r = tt >> 5, c4 = tt & 31;
            float4 val = ((const float4*)(vb + (size_t)(n0 + r) * Dd))[c4];
            *(float4*)&Ks[r * KSTRIDE + c4 * 4] = val;
        }
        __syncthreads();

        // O += P @ V (4 keys per step, float4 P loads)
        #pragma unroll 4
        for (int n4 = 0; n4 < BN; n4 += 4) {
            float pr[4][4];
            #pragma unroll
            for (int a = 0; a < 4; a++) {
                float4 p4 = *(const float4*)&Ps[(ty + 16 * a) * PSTRIDE + n4];
                pr[a][0] = p4.x; pr[a][1] = p4.y; pr[a][2] = p4.z; pr[a][3] = p4.w;
            }
            #pragma unroll
            for (int nn = 0; nn < 4; nn++) {
                float vv[8];
                #pragma unroll
                for (int j = 0; j < 8; j++)
                    vv[j] = Ks[(n4 + nn) * KSTRIDE + tx + 16 * j];
                #pragma unroll
                for (int a = 0; a < 4; a++)
                    #pragma unroll
                    for (int j = 0; j < 8; j++)
                        O[a][j] = fmaf(pr[a][nn], vv[j], O[a][j]);
            }
        }
    }

    // Normalize + write out
    #pragma unroll
    for (int a = 0; a < 4; a++) {
        float inv = (l[a] > 0.f) ? (1.f / l[a]) : 0.f;
        const int i = ty + 16 * a;
        #pragma unroll
        for (int j = 0; j < 8; j++)
            ob[(size_t)i * Dd + tx + 16 * j] = O[a][j] * inv;
    }
}

extern "C" void kernel_launch(void* const* d_in, const int* in_sizes, int n_in,
                              void* d_out, int out_size) {
    const float* q = (const float*)d_in[0];
    const float* k = (const float*)d_in[1];
    const float* v = (const float*)d_in[2];
    const unsigned char* mask = (const unsigned char*)d_in[3];
    const float* bias = (const float*)d_in[4];
    const int* off = (n_in > 5) ? (const int*)d_in[5] : nullptr;
    float* out = (float*)d_out;

    cudaFuncSetAttribute(attend_kernel,
                         cudaFuncAttributeMaxDynamicSharedMemorySize, SMEM_BYTES);

    prep_kernel<<<Bb, 256>>>(mask, off);
    dim3 grid(Ss / BM, Bb * Hh);
    attend_kernel<<<grid, NT, SMEM_BYTES>>>(q, k, v, bias, out);
}